// round 17
// baseline (speedup 1.0000x reference)
#include <cuda_runtime.h>
#include <cuda_bf16.h>

#define NB 64
#define NT 512
#define ND 1024
#define BPB 16  // batches per block in kernel B

// scratch: packed (chain_pos | role<<16) per (b,t). Static device global.
__device__ int g_packed[NB * NT];

// ---------------------------------------------------------------------------
// Kernel A: warp-sequential scan, one warp per batch row. No barriers, no
// smem. All 32 chunk-loads issued up front (MLP=32), then 16 ballot/popc
// steps. cumsum: popc of masked inc-ballot. cummax: since c is nondecreasing,
// inclusive cummax = c_excl at the LATEST reset <= pos (clz on reset-ballot),
// carried across chunks.
// ---------------------------------------------------------------------------
__global__ __launch_bounds__(128) void gpe_scan_kernel(
    const int* __restrict__ input_ids,
    const int* __restrict__ rel_ids) {

    const int tid = threadIdx.x;
    const int lane = tid & 31;
    const int b = blockIdx.x * 4 + (tid >> 5);   // 16 blocks * 4 warps = 64

    int rel[16], id[16];
#pragma unroll
    for (int k = 0; k < 16; k++) {
        rel[k] = rel_ids[b * NT + k * 32 + lane];
        id[k]  = input_ids[b * NT + k * 32 + lane];
    }

    const unsigned ltmask = (1u << lane) - 1u;

    int base_cnt = 0;        // count of rel>0 in chunks < k
    int baseline_carry = 0;  // cummax carried from earlier chunks
    int last_rel = 0;        // rel at global position (k*32 - 1); 0 before t=0

#pragma unroll
    for (int k = 0; k < 16; k++) {
        const int r = rel[k];
        const unsigned bal_inc = __ballot_sync(0xFFFFFFFFu, r > 0);

        int prev = __shfl_up_sync(0xFFFFFFFFu, r, 1);
        if (lane == 0) prev = last_rel;
        const bool reset = (r == 0) && (prev > 0);
        const unsigned bal_rst = __ballot_sync(0xFFFFFFFFu, reset);

        // exclusive count of rel>0 at this position
        const int c_ex = base_cnt + __popc(bal_inc & ltmask);

        // baseline = c_excl at latest reset <= pos (inclusive), else carry
        const unsigned r_le = bal_rst & (ltmask | (1u << lane));
        int baseline;
        if (r_le) {
            const int j = 31 - __clz(r_le);
            baseline = base_cnt + __popc(bal_inc & ((1u << j) - 1u));
        } else {
            baseline = baseline_carry;
        }
        const int cp = c_ex - baseline;

        const int role = (id[k] <= 4) ? 3 : ((r == 0) ? 2 : 0);
        g_packed[b * NT + k * 32 + lane] = cp | (role << 16);

        // carries (uniform across warp)
        if (bal_rst) {
            const int jm = 31 - __clz(bal_rst);
            baseline_carry = base_cnt + __popc(bal_inc & ((1u << jm) - 1u));
        }
        base_cnt += __popc(bal_inc);
        last_rel = __shfl_sync(0xFFFFFFFFu, r, 31);
    }
}

// streaming (evict-first) float4 store
__device__ __forceinline__ void stcs4(float4* p, float4 v) {
    asm volatile("st.global.cs.v4.f32 [%0], {%1,%2,%3,%4};"
                 :: "l"(p), "f"(v.x), "f"(v.y), "f"(v.z), "f"(v.w) : "memory");
}

// ---------------------------------------------------------------------------
// Kernel B: embedding sum with PDL. The 5 table-row loads are issued BEFORE
// cudaGridDependencySynchronize(); only the g_packed read waits for the
// scan — overlapping emb's launch+preamble with the (now ~0.5us) scan.
// Grid (NT, NB/BPB) = (512, 4), 256 threads/block.
// ---------------------------------------------------------------------------
__global__ __launch_bounds__(256) void gpe_emb_kernel(
    const float* __restrict__ seq_table,
    const float* __restrict__ chain_table,
    const float* __restrict__ depth_table,
    const float* __restrict__ role_table,
    float* __restrict__ out) {

    const int t = blockIdx.x;
    const int b0 = blockIdx.y * BPB;
    const int tid = threadIdx.x;
    const int d = tid * 4;

    __shared__ int spk[BPB];

    // ---- independent-of-scan preamble: issue table loads first ----
    const float4 s4 = *(const float4*)(seq_table + (size_t)t * ND + d);
    const float4 dp = *(const float4*)(depth_table + d);  // depth row 0 always
    float4 r0 = *(const float4*)(role_table + 0 * ND + d);
    float4 r2 = *(const float4*)(role_table + 2 * ND + d);
    float4 r3 = *(const float4*)(role_table + 3 * ND + d);

    float4 base;
    base.x = s4.x + 0.3f * dp.x;
    base.y = s4.y + 0.3f * dp.y;
    base.z = s4.z + 0.3f * dp.z;
    base.w = s4.w + 0.3f * dp.w;
    r0.x *= 0.2f; r0.y *= 0.2f; r0.z *= 0.2f; r0.w *= 0.2f;
    r2.x *= 0.2f; r2.y *= 0.2f; r2.z *= 0.2f; r2.w *= 0.2f;
    r3.x *= 0.2f; r3.y *= 0.2f; r3.z *= 0.2f; r3.w *= 0.2f;

    // ---- wait for the scan kernel's results, then read g_packed ----
    cudaGridDependencySynchronize();
    if (tid < BPB) spk[tid] = g_packed[(b0 + tid) * NT + t];
    __syncthreads();

#pragma unroll 8
    for (int i = 0; i < BPB; i++) {
        const int pk = spk[i];
        const int cp = pk & 0xFFFF;
        const int role = pk >> 16;

        const float4 c4 = *(const float4*)(chain_table + (size_t)cp * ND + d);
        const float4 r4 = (role == 3) ? r3 : ((role == 2) ? r2 : r0);

        float4 o;
        o.x = base.x + 0.5f * c4.x + r4.x;
        o.y = base.y + 0.5f * c4.y + r4.y;
        o.z = base.z + 0.5f * c4.z + r4.z;
        o.w = base.w + 0.5f * c4.w + r4.w;

        stcs4((float4*)(out + ((size_t)(b0 + i) * NT + t) * ND + d), o);
    }
}

extern "C" void kernel_launch(void* const* d_in, const int* in_sizes, int n_in,
                              void* d_out, int out_size) {
    const int* input_ids   = (const int*)d_in[0];
    const int* rel_ids     = (const int*)d_in[1];
    const float* seq_table = (const float*)d_in[2];
    const float* chain_tab = (const float*)d_in[3];
    const float* depth_tab = (const float*)d_in[4];
    const float* role_tab  = (const float*)d_in[5];
    float* out = (float*)d_out;

    gpe_scan_kernel<<<16, 128>>>(input_ids, rel_ids);

    cudaLaunchConfig_t cfg = {};
    cfg.gridDim = dim3(NT, NB / BPB);
    cfg.blockDim = dim3(256);
    cfg.dynamicSmemBytes = 0;
    cfg.stream = 0;
    cudaLaunchAttribute attr[1];
    attr[0].id = cudaLaunchAttributeProgrammaticStreamSerialization;
    attr[0].val.programmaticStreamSerializationAllowed = 1;
    cfg.attrs = attr;
    cfg.numAttrs = 1;
    cudaLaunchKernelEx(&cfg, gpe_emb_kernel,
                       seq_table, chain_tab, depth_tab, role_tab, out);
}